// round 7
// baseline (speedup 1.0000x reference)
#include <cuda_runtime.h>
#include <cuda_fp16.h>
#include <math.h>
#include <stdint.h>

#define N_CELLS 16384
#define H 512
#define D 512
#define KNB 15

// ---------------- scratch ----------------
// v = sqrt(|s|) * unit(s)  packed half2 (re,im).
__device__ __align__(16) __half2 g_v  [N_CELLS * H];
__device__ __align__(16) __half2 g_new[N_CELLS * H];
__device__ int    g_lasing[N_CELLS];
__device__ int    g_nlasing;
__device__ float  g_em_re[H];
__device__ float  g_em_im[H];
__device__ float  g_cavn_re[H];
__device__ float  g_cavn_im[H];
__device__ float  g_cav_phase[H];
__device__ double g_sum, g_sum2;
__device__ unsigned int g_done;

// ---------------- K1: pump -> lasing mask ----------------
__global__ void k_pump(const float* __restrict__ x,
                       const float* __restrict__ W,
                       const float* __restrict__ b,
                       const float* __restrict__ excited) {
    int gwarp = (blockIdx.x * blockDim.x + threadIdx.x) >> 5;
    int lane  = threadIdx.x & 31;
    if (gwarp >= N_CELLS) return;
    const float* w = W + (size_t)gwarp * D;
    float s = 0.f;
#pragma unroll
    for (int t = 0; t < D / 32; t++)
        s += x[lane + 32 * t] * w[lane + 32 * t];
#pragma unroll
    for (int o = 16; o; o >>= 1) s += __shfl_xor_sync(0xFFFFFFFFu, s, o);
    if (lane == 0) {
        float z = s + b[gwarp];
        float pump = 1.f / (1.f + expf(-z));
        float e = excited[gwarp] * 0.95f + pump * 0.05f;
        e = fminf(fmaxf(e, 0.f), 1.f);
        g_lasing[gwarp] = (e > 0.5f) ? 1 : 0;
    }
}

// ---------------- K2: rotate (Taylor) + scale to v = s/sqrt(|s|) ----------------
__global__ void k_rot(const float4* __restrict__ cr,
                      const float4* __restrict__ ci,
                      const float4* __restrict__ pv) {
    int i = blockIdx.x * blockDim.x + threadIdx.x;   // over N*H/4
    if (blockIdx.x == 0) {
        for (int j = threadIdx.x; j < H; j += blockDim.x) {
            g_em_re[j] = 0.f; g_em_im[j] = 0.f;
        }
        if (threadIdx.x == 0) {
            g_nlasing = 0; g_sum = 0.0; g_sum2 = 0.0; g_done = 0u;
        }
    }
    if (i >= (N_CELLS * H) / 4) return;
    float4 a4 = cr[i], b4 = ci[i], p4 = pv[i];
    float ax[4] = {a4.x, a4.y, a4.z, a4.w};
    float bx[4] = {b4.x, b4.y, b4.z, b4.w};
    float px[4] = {p4.x, p4.y, p4.z, p4.w};
    uint4 outp;
    unsigned int* op = (unsigned int*)&outp;
#pragma unroll
    for (int q = 0; q < 4; q++) {
        float ang = 0.1f * px[q];
        float a2 = ang * ang;
        float cs = 1.f - 0.5f * a2;                 // |ang| small: err ~1e-7
        float sn = ang * (1.f - a2 * (1.f / 6.f));
        float re = ax[q] * cs - bx[q] * sn;
        float im = ax[q] * sn + bx[q] * cs;
        float m2 = fmaxf(re * re + im * im, 1e-30f);
        float qm = rsqrtf(sqrtf(m2));               // |s|^(-1/2)
        __half2 h = __floats2half2_rn(re * qm, im * qm);
        op[q] = *(unsigned int*)&h;
    }
    *(uint4*)((unsigned int*)g_v + (size_t)i * 4) = outp;
}

// ---------------- K3: neighbor coupling (Gram-matrix form, half2 SIMD) -------
// A = sum_j v_j v_j^T per channel (2x2 sym).  new = 0.7|v|v + CF*(A v)/|v|
__global__ void __launch_bounds__(128) k_couple(const int* __restrict__ nbr) {
    int cell = blockIdx.x;
    int t = threadIdx.x;
    __shared__ int snb[16];
    if (t < KNB) snb[t] = nbr[cell * KNB + t];
    __syncthreads();

    int chbase = t * 4;
    const __half2 z2 = __floats2half2_rn(0.f, 0.f);
    __half2 sq0 = z2, sq1 = z2, sq2 = z2, sq3 = z2;  // (Σnx², Σny²) per channel
    __half2 xy01 = z2, xy23 = z2;                    // Σnx·ny packed channel-pairs

#pragma unroll 3
    for (int j = 0; j < KNB; j++) {
        const uint4 np = *(const uint4*)(g_v + (size_t)snb[j] * H + chbase);
        __half2 n0 = *(const __half2*)&np.x;
        __half2 n1 = *(const __half2*)&np.y;
        __half2 n2 = *(const __half2*)&np.z;
        __half2 n3 = *(const __half2*)&np.w;
        sq0 = __hfma2(n0, n0, sq0);
        sq1 = __hfma2(n1, n1, sq1);
        sq2 = __hfma2(n2, n2, sq2);
        sq3 = __hfma2(n3, n3, sq3);
        unsigned int p, q;
        p = __byte_perm(np.x, np.y, 0x5410);  // (n0x, n1x)
        q = __byte_perm(np.x, np.y, 0x7632);  // (n0y, n1y)
        xy01 = __hfma2(*(__half2*)&p, *(__half2*)&q, xy01);
        p = __byte_perm(np.z, np.w, 0x5410);
        q = __byte_perm(np.z, np.w, 0x7632);
        xy23 = __hfma2(*(__half2*)&p, *(__half2*)&q, xy23);
    }

    size_t base = (size_t)cell * H + chbase;
    uint4 vp = *(const uint4*)(g_v + base);
    float2 v[4];
    v[0] = __half22float2(*(const __half2*)&vp.x);
    v[1] = __half22float2(*(const __half2*)&vp.y);
    v[2] = __half22float2(*(const __half2*)&vp.z);
    v[3] = __half22float2(*(const __half2*)&vp.w);

    float2 sqf[4];
    sqf[0] = __half22float2(sq0); sqf[1] = __half22float2(sq1);
    sqf[2] = __half22float2(sq2); sqf[3] = __half22float2(sq3);
    float2 xya = __half22float2(xy01);
    float2 xyb = __half22float2(xy23);
    float sxy[4] = {xya.x, xya.y, xyb.x, xyb.y};

    const float CF = 0.3f * 0.1f / (float)KNB;  // 0.002
    uint4 outp;
    unsigned int* op = (unsigned int*)&outp;
#pragma unroll
    for (int qc = 0; qc < 4; qc++) {
        float vx = v[qc].x, vy = v[qc].y;
        float ir = vx * sqf[qc].x + vy * sxy[qc];     // (A v).re
        float ii = vx * sxy[qc]   + vy * sqf[qc].y;   // (A v).im
        float a2 = fmaxf(vx * vx + vy * vy, 1e-30f);
        float inv = rsqrtf(a2);
        float amp = a2 * inv;                          // |v|
        __half2 h = __floats2half2_rn(0.7f * amp * vx + CF * inv * ir,
                                      0.7f * amp * vy + CF * inv * ii);
        op[qc] = *(unsigned int*)&h;
    }
    *(uint4*)(g_new + base) = outp;
}

// ---------------- K4: emission (hierarchical, 1024 blocks) + lasing count ----
__global__ void __launch_bounds__(128) k_emit() {
    int t = threadIdx.x;
    int c0 = blockIdx.x * 16;
    __shared__ int smask[16];
    if (t < 16) smask[t] = g_lasing[c0 + t];
    __syncthreads();
    if (t < 32) {
        int c = (t < 16) ? smask[t] : 0;
#pragma unroll
        for (int o = 16; o; o >>= 1) c += __shfl_xor_sync(0xFFFFFFFFu, c, o);
        if (t == 0 && c) atomicAdd(&g_nlasing, c);
    }

    float sr0 = 0, sr1 = 0, sr2 = 0, sr3 = 0, si0 = 0, si1 = 0, si2 = 0, si3 = 0;
    int any = 0;
#pragma unroll 4
    for (int c = 0; c < 16; c++) {
        if (smask[c]) {
            any = 1;
            size_t base = (size_t)(c0 + c) * H + (size_t)t * 4;
            uint4 p = *(const uint4*)(g_new + base);
            float2 c0v = __half22float2(*(const __half2*)&p.x);
            float2 c1v = __half22float2(*(const __half2*)&p.y);
            float2 c2v = __half22float2(*(const __half2*)&p.z);
            float2 c3v = __half22float2(*(const __half2*)&p.w);
            sr0 += c0v.x; si0 += c0v.y;
            sr1 += c1v.x; si1 += c1v.y;
            sr2 += c2v.x; si2 += c2v.y;
            sr3 += c3v.x; si3 += c3v.y;
        }
    }
    if (any) {
        int h = t * 4;
        atomicAdd(&g_em_re[h + 0], sr0); atomicAdd(&g_em_re[h + 1], sr1);
        atomicAdd(&g_em_re[h + 2], sr2); atomicAdd(&g_em_re[h + 3], sr3);
        atomicAdd(&g_em_im[h + 0], si0); atomicAdd(&g_em_im[h + 1], si1);
        atomicAdd(&g_em_im[h + 2], si2); atomicAdd(&g_em_im[h + 3], si3);
    }
}

// ---------------- K5a: cavity update ----------------
__global__ void __launch_bounds__(512) k_cav_update(const float* __restrict__ cav_re,
                                                    const float* __restrict__ cav_im) {
    int t = threadIdx.x;
    int nl = g_nlasing;
    float inv = 1.f / fmaxf((float)nl, 1.f);
    float cr = cav_re[t], ci = cav_im[t];
    float nr = (nl > 0) ? 0.8f * cr + 0.2f * (g_em_re[t] * inv) : cr;
    float ni = (nl > 0) ? 0.8f * ci + 0.2f * (g_em_im[t] * inv) : ci;
    g_cavn_re[t] = nr;
    g_cavn_im[t] = ni;
    g_cav_phase[t] = atan2f(ci, cr);   // OLD cavity phase
}

// ---------------- K5b: decode GEMV ----------------
__global__ void __launch_bounds__(128) k_decode(const float* __restrict__ decW,
                                                const float* __restrict__ decb,
                                                float* __restrict__ out) {
    int d = blockIdx.x;
    int t = threadIdx.x;
    const float* w = decW + (size_t)d * (2 * H);
    float s = 0.f;
#pragma unroll
    for (int j = t; j < 2 * H; j += 128) {
        float v = (j < H) ? g_cavn_re[j] : g_cavn_im[j - H];
        s = fmaf(v, w[j], s);
    }
#pragma unroll
    for (int o = 16; o; o >>= 1) s += __shfl_xor_sync(0xFFFFFFFFu, s, o);
    __shared__ float red[4];
    if ((t & 31) == 0) red[t >> 5] = s;
    __syncthreads();
    if (t == 0) out[d] = red[0] + red[1] + red[2] + red[3] + decb[d];
}

// ---------------- K6: finalize + variance + fused tension (shuffle reductions)
__global__ void __launch_bounds__(128) k_final(float* __restrict__ out, int out_size) {
    int cell = blockIdx.x;
    int t = threadIdx.x;
    int wid = t >> 5, lane = t & 31;
    __shared__ float wmax[4];
    __shared__ float ws[4], ws2[4];

    size_t base = (size_t)cell * H + (size_t)t * 4;
    uint4 p = *(const uint4*)(g_new + base);
    float2 c0 = __half22float2(*(const __half2*)&p.x);
    float2 c1 = __half22float2(*(const __half2*)&p.y);
    float2 c2 = __half22float2(*(const __half2*)&p.z);
    float2 c3 = __half22float2(*(const __half2*)&p.w);
    int las = g_lasing[cell];

    float amp[4];
    float re_[4] = {c0.x, c1.x, c2.x, c3.x};
    float im_[4] = {c0.y, c1.y, c2.y, c3.y};
    float mx = 0.f;
#pragma unroll
    for (int q = 0; q < 4; q++) {
        int h = t * 4 + q;
        float re = re_[q], im = im_[q];
        if (las) {
            float a = sqrtf(re * re + im * im);
            float ang = 0.3f * g_cav_phase[h] + 0.7f * atan2f(im, re);
            float sn, cs;
            __sincosf(ang, &sn, &cs);
            re = a * cs;
            im = a * sn;
        }
        re += 0.05f * g_cavn_re[h];
        im += 0.05f * g_cavn_im[h];
        amp[q] = sqrtf(re * re + im * im);
        mx = fmaxf(mx, amp[q]);
    }
#pragma unroll
    for (int o = 16; o; o >>= 1) mx = fmaxf(mx, __shfl_xor_sync(0xFFFFFFFFu, mx, o));
    if (lane == 0) wmax[wid] = mx;
    __syncthreads();
    float bmax = fmaxf(fmaxf(wmax[0], wmax[1]), fmaxf(wmax[2], wmax[3]));
    float inv = 1.f / (bmax + 1e-8f);

    float s = 0.f, s2 = 0.f;
#pragma unroll
    for (int q = 0; q < 4; q++) {
        float an = amp[q] * inv;
        s += an;
        s2 = fmaf(an, an, s2);
    }
#pragma unroll
    for (int o = 16; o; o >>= 1) {
        s  += __shfl_xor_sync(0xFFFFFFFFu, s, o);
        s2 += __shfl_xor_sync(0xFFFFFFFFu, s2, o);
    }
    if (lane == 0) { ws[wid] = s; ws2[wid] = s2; }
    __syncthreads();
    if (t == 0) {
        float bs  = ws[0] + ws[1] + ws[2] + ws[3];
        float bs2 = ws2[0] + ws2[1] + ws2[2] + ws2[3];
        atomicAdd(&g_sum,  (double)bs);
        atomicAdd(&g_sum2, (double)bs2);
        __threadfence();
        unsigned int done = atomicAdd(&g_done, 1u);
        if (done == gridDim.x - 1) {
            double S  = atomicAdd(&g_sum,  0.0);   // coherent read-back
            double S2 = atomicAdd(&g_sum2, 0.0);
            double M = (double)N_CELLS * (double)H;
            double mean = S / M;
            double var = S2 / M - mean * mean;
            out[out_size - 1] = (float)var;
        }
    }
}

// ---------------- launcher ----------------
extern "C" void kernel_launch(void* const* d_in, const int* in_sizes, int n_in,
                              void* d_out, int out_size) {
    const float* x       = (const float*)d_in[0];
    const float* pump_W  = (const float*)d_in[1];
    const float* pump_b  = (const float*)d_in[2];
    const float* dec_W   = (const float*)d_in[3];
    const float* dec_b   = (const float*)d_in[4];
    const float* cs_re   = (const float*)d_in[5];
    const float* cs_im   = (const float*)d_in[6];
    const float* excited = (const float*)d_in[7];
    const float* phase_v = (const float*)d_in[8];
    const float* cav_re  = (const float*)d_in[9];
    const float* cav_im  = (const float*)d_in[10];
    const int*   nbr     = (const int*)d_in[11];
    float* out = (float*)d_out;

    k_rot<<<(N_CELLS * H / 4) / 256, 256>>>((const float4*)cs_re,
                                            (const float4*)cs_im,
                                            (const float4*)phase_v);
    k_pump<<<(N_CELLS * 32) / 256, 256>>>(x, pump_W, pump_b, excited);
    k_couple<<<N_CELLS, 128>>>(nbr);
    k_emit<<<N_CELLS / 16, 128>>>();
    k_cav_update<<<1, 512>>>(cav_re, cav_im);
    k_decode<<<D, 128>>>(dec_W, dec_b, out);
    k_final<<<N_CELLS, 128>>>(out, out_size);
}

// round 9
// speedup vs baseline: 1.1443x; 1.1443x over previous
#include <cuda_runtime.h>
#include <cuda_fp16.h>
#include <math.h>
#include <stdint.h>

#define N_CELLS 16384
#define H 512
#define D 512
#define KNB 15

// ---------------- scratch ----------------
__device__ __align__(16) __half2 g_v  [N_CELLS * H];   // v = sqrt(|s|)*unit(s)
__device__ __align__(16) __half2 g_new[N_CELLS * H];
__device__ int    g_lasing[N_CELLS];
__device__ int    g_las_list[N_CELLS];
__device__ int    g_nlasing;
__device__ float  g_em_re[H];
__device__ float  g_em_im[H];
__device__ float  g_cavn_re[H];
__device__ float  g_cavn_im[H];
__device__ float  g_cav_phase[H];
__device__ double g_sum, g_sum2;
__device__ unsigned int g_done;

// ---------------- K1: pump -> lasing mask + compaction ----------------
// 256 threads = 8 warps = 8 cells per block
__global__ void k_pump(const float* __restrict__ x,
                       const float* __restrict__ W,
                       const float* __restrict__ b,
                       const float* __restrict__ excited) {
    int warp = threadIdx.x >> 5;
    int lane = threadIdx.x & 31;
    int cell = blockIdx.x * 8 + warp;
    const float* w = W + (size_t)cell * D;
    float s = 0.f;
#pragma unroll
    for (int t = 0; t < D / 32; t++)
        s += x[lane + 32 * t] * w[lane + 32 * t];
#pragma unroll
    for (int o = 16; o; o >>= 1) s += __shfl_xor_sync(0xFFFFFFFFu, s, o);

    __shared__ int sflag[8];
    __shared__ int sbase;
    if (lane == 0) {
        float z = s + b[cell];
        float pump = 1.f / (1.f + expf(-z));
        float e = excited[cell] * 0.95f + pump * 0.05f;
        e = fminf(fmaxf(e, 0.f), 1.f);
        int las = (e > 0.5f) ? 1 : 0;
        g_lasing[cell] = las;
        sflag[warp] = las;
    }
    __syncthreads();
    if (threadIdx.x < 8) {
        unsigned m = __ballot_sync(0x000000FFu, sflag[threadIdx.x]);
        int total = __popc(m);
        if (threadIdx.x == 0 && total) sbase = atomicAdd(&g_nlasing, total);
        __syncwarp(0x000000FFu);
        if (sflag[threadIdx.x]) {
            int pos = sbase + __popc(m & ((1u << threadIdx.x) - 1u));
            g_las_list[pos] = blockIdx.x * 8 + threadIdx.x;
        }
    }
}

// ---------------- K2: rotate (Taylor) + scale to v = s/sqrt(|s|) ----------------
__global__ void k_rot(const float4* __restrict__ cr,
                      const float4* __restrict__ ci,
                      const float4* __restrict__ pv) {
    int i = blockIdx.x * blockDim.x + threadIdx.x;   // over N*H/4
    if (blockIdx.x == 0) {
        for (int j = threadIdx.x; j < H; j += blockDim.x) {
            g_em_re[j] = 0.f; g_em_im[j] = 0.f;
        }
        if (threadIdx.x == 0) {
            g_nlasing = 0; g_sum = 0.0; g_sum2 = 0.0; g_done = 0u;
        }
    }
    if (i >= (N_CELLS * H) / 4) return;
    float4 a4 = cr[i], b4 = ci[i], p4 = pv[i];
    float ax[4] = {a4.x, a4.y, a4.z, a4.w};
    float bx[4] = {b4.x, b4.y, b4.z, b4.w};
    float px[4] = {p4.x, p4.y, p4.z, p4.w};
    uint4 outp;
    unsigned int* op = (unsigned int*)&outp;
#pragma unroll
    for (int q = 0; q < 4; q++) {
        float ang = 0.1f * px[q];
        float a2 = ang * ang;
        float cs = 1.f - 0.5f * a2;
        float sn = ang * (1.f - a2 * (1.f / 6.f));
        float re = ax[q] * cs - bx[q] * sn;
        float im = ax[q] * sn + bx[q] * cs;
        float m2 = fmaxf(re * re + im * im, 1e-30f);
        float qm = rsqrtf(sqrtf(m2));               // |s|^(-1/2)
        __half2 h = __floats2half2_rn(re * qm, im * qm);
        op[q] = *(unsigned int*)&h;
    }
    *(uint4*)((unsigned int*)g_v + (size_t)i * 4) = outp;
}

// ---------------- K3: neighbor coupling (Gram-matrix, half2 SIMD) ----------
__global__ void __launch_bounds__(128) k_couple(const int* __restrict__ nbr) {
    int cell = blockIdx.x;
    int t = threadIdx.x;
    __shared__ int snb[16];
    if (t < KNB) snb[t] = nbr[cell * KNB + t];
    __syncthreads();

    int chbase = t * 4;
    const __half2 z2 = __floats2half2_rn(0.f, 0.f);
    __half2 sq0 = z2, sq1 = z2, sq2 = z2, sq3 = z2;
    __half2 xy01 = z2, xy23 = z2;

#pragma unroll 3
    for (int j = 0; j < KNB; j++) {
        const uint4 np = *(const uint4*)(g_v + (size_t)snb[j] * H + chbase);
        __half2 n0 = *(const __half2*)&np.x;
        __half2 n1 = *(const __half2*)&np.y;
        __half2 n2 = *(const __half2*)&np.z;
        __half2 n3 = *(const __half2*)&np.w;
        sq0 = __hfma2(n0, n0, sq0);
        sq1 = __hfma2(n1, n1, sq1);
        sq2 = __hfma2(n2, n2, sq2);
        sq3 = __hfma2(n3, n3, sq3);
        unsigned int p, q;
        p = __byte_perm(np.x, np.y, 0x5410);
        q = __byte_perm(np.x, np.y, 0x7632);
        xy01 = __hfma2(*(__half2*)&p, *(__half2*)&q, xy01);
        p = __byte_perm(np.z, np.w, 0x5410);
        q = __byte_perm(np.z, np.w, 0x7632);
        xy23 = __hfma2(*(__half2*)&p, *(__half2*)&q, xy23);
    }

    size_t base = (size_t)cell * H + chbase;
    uint4 vp = *(const uint4*)(g_v + base);
    float2 v[4];
    v[0] = __half22float2(*(const __half2*)&vp.x);
    v[1] = __half22float2(*(const __half2*)&vp.y);
    v[2] = __half22float2(*(const __half2*)&vp.z);
    v[3] = __half22float2(*(const __half2*)&vp.w);

    float2 sqf[4];
    sqf[0] = __half22float2(sq0); sqf[1] = __half22float2(sq1);
    sqf[2] = __half22float2(sq2); sqf[3] = __half22float2(sq3);
    float2 xya = __half22float2(xy01);
    float2 xyb = __half22float2(xy23);
    float sxy[4] = {xya.x, xya.y, xyb.x, xyb.y};

    const float CF = 0.3f * 0.1f / (float)KNB;  // 0.002
    uint4 outp;
    unsigned int* op = (unsigned int*)&outp;
#pragma unroll
    for (int qc = 0; qc < 4; qc++) {
        float vx = v[qc].x, vy = v[qc].y;
        float ir = vx * sqf[qc].x + vy * sxy[qc];
        float ii = vx * sxy[qc]   + vy * sqf[qc].y;
        float a2 = fmaxf(vx * vx + vy * vy, 1e-30f);
        float inv = rsqrtf(a2);
        float amp = a2 * inv;
        __half2 h = __floats2half2_rn(0.7f * amp * vx + CF * inv * ir,
                                      0.7f * amp * vy + CF * inv * ii);
        op[qc] = *(unsigned int*)&h;
    }
    *(uint4*)(g_new + base) = outp;
}

// ---------------- K4: emission over compacted lasing list ----------------
// grid = 64 blocks x 128 threads; block strides the list
__global__ void __launch_bounds__(128) k_emit() {
    int t = threadIdx.x;
    int nl = g_nlasing;
    float sr0 = 0, sr1 = 0, sr2 = 0, sr3 = 0, si0 = 0, si1 = 0, si2 = 0, si3 = 0;
    int any = 0;
    for (int i = blockIdx.x; i < nl; i += gridDim.x) {
        any = 1;
        int cell = g_las_list[i];
        size_t base = (size_t)cell * H + (size_t)t * 4;
        uint4 p = *(const uint4*)(g_new + base);
        float2 c0v = __half22float2(*(const __half2*)&p.x);
        float2 c1v = __half22float2(*(const __half2*)&p.y);
        float2 c2v = __half22float2(*(const __half2*)&p.z);
        float2 c3v = __half22float2(*(const __half2*)&p.w);
        sr0 += c0v.x; si0 += c0v.y;
        sr1 += c1v.x; si1 += c1v.y;
        sr2 += c2v.x; si2 += c2v.y;
        sr3 += c3v.x; si3 += c3v.y;
    }
    if (any) {
        int h = t * 4;
        atomicAdd(&g_em_re[h + 0], sr0); atomicAdd(&g_em_re[h + 1], sr1);
        atomicAdd(&g_em_re[h + 2], sr2); atomicAdd(&g_em_re[h + 3], sr3);
        atomicAdd(&g_em_im[h + 0], si0); atomicAdd(&g_em_im[h + 1], si1);
        atomicAdd(&g_em_im[h + 2], si2); atomicAdd(&g_em_im[h + 3], si3);
    }
}

// ---------------- K5a: cavity update ----------------
__global__ void __launch_bounds__(512) k_cav_update(const float* __restrict__ cav_re,
                                                    const float* __restrict__ cav_im) {
    int t = threadIdx.x;
    int nl = g_nlasing;
    float inv = 1.f / fmaxf((float)nl, 1.f);
    float cr = cav_re[t], ci = cav_im[t];
    float nr = (nl > 0) ? 0.8f * cr + 0.2f * (g_em_re[t] * inv) : cr;
    float ni = (nl > 0) ? 0.8f * ci + 0.2f * (g_em_im[t] * inv) : ci;
    g_cavn_re[t] = nr;
    g_cavn_im[t] = ni;
    g_cav_phase[t] = atan2f(ci, cr);   // OLD cavity phase
}

// ---------------- K5b: decode GEMV ----------------
__global__ void __launch_bounds__(128) k_decode(const float* __restrict__ decW,
                                                const float* __restrict__ decb,
                                                float* __restrict__ out) {
    int d = blockIdx.x;
    int t = threadIdx.x;
    const float* w = decW + (size_t)d * (2 * H);
    float s = 0.f;
#pragma unroll
    for (int j = t; j < 2 * H; j += 128) {
        float v = (j < H) ? g_cavn_re[j] : g_cavn_im[j - H];
        s = fmaf(v, w[j], s);
    }
#pragma unroll
    for (int o = 16; o; o >>= 1) s += __shfl_xor_sync(0xFFFFFFFFu, s, o);
    __shared__ float red[4];
    if ((t & 31) == 0) red[t >> 5] = s;
    __syncthreads();
    if (t == 0) out[d] = red[0] + red[1] + red[2] + red[3] + decb[d];
}

// ---------------- K6: finalize + variance + fused tension ----------------
__global__ void __launch_bounds__(128) k_final(float* __restrict__ out, int out_size) {
    int cell = blockIdx.x;
    int t = threadIdx.x;
    int wid = t >> 5, lane = t & 31;
    __shared__ float wmax[4];
    __shared__ float ws[4], ws2[4];

    size_t base = (size_t)cell * H + (size_t)t * 4;
    uint4 p = *(const uint4*)(g_new + base);
    float2 c0 = __half22float2(*(const __half2*)&p.x);
    float2 c1 = __half22float2(*(const __half2*)&p.y);
    float2 c2 = __half22float2(*(const __half2*)&p.z);
    float2 c3 = __half22float2(*(const __half2*)&p.w);
    int las = g_lasing[cell];

    float amp[4];
    float re_[4] = {c0.x, c1.x, c2.x, c3.x};
    float im_[4] = {c0.y, c1.y, c2.y, c3.y};
    float mx = 0.f;
#pragma unroll
    for (int q = 0; q < 4; q++) {
        int h = t * 4 + q;
        float re = re_[q], im = im_[q];
        if (las) {
            float a = sqrtf(re * re + im * im);
            float ang = 0.3f * g_cav_phase[h] + 0.7f * atan2f(im, re);
            float sn, cs;
            __sincosf(ang, &sn, &cs);
            re = a * cs;
            im = a * sn;
        }
        re += 0.05f * g_cavn_re[h];
        im += 0.05f * g_cavn_im[h];
        amp[q] = sqrtf(re * re + im * im);
        mx = fmaxf(mx, amp[q]);
    }
#pragma unroll
    for (int o = 16; o; o >>= 1) mx = fmaxf(mx, __shfl_xor_sync(0xFFFFFFFFu, mx, o));
    if (lane == 0) wmax[wid] = mx;
    __syncthreads();
    float bmax = fmaxf(fmaxf(wmax[0], wmax[1]), fmaxf(wmax[2], wmax[3]));
    float inv = 1.f / (bmax + 1e-8f);

    float s = 0.f, s2 = 0.f;
#pragma unroll
    for (int q = 0; q < 4; q++) {
        float an = amp[q] * inv;
        s += an;
        s2 = fmaf(an, an, s2);
    }
#pragma unroll
    for (int o = 16; o; o >>= 1) {
        s  += __shfl_xor_sync(0xFFFFFFFFu, s, o);
        s2 += __shfl_xor_sync(0xFFFFFFFFu, s2, o);
    }
    if (lane == 0) { ws[wid] = s; ws2[wid] = s2; }
    __syncthreads();
    if (t == 0) {
        float bs  = ws[0] + ws[1] + ws[2] + ws[3];
        float bs2 = ws2[0] + ws2[1] + ws2[2] + ws2[3];
        atomicAdd(&g_sum,  (double)bs);
        atomicAdd(&g_sum2, (double)bs2);
        __threadfence();
        unsigned int done = atomicAdd(&g_done, 1u);
        if (done == gridDim.x - 1) {
            double S  = atomicAdd(&g_sum,  0.0);
            double S2 = atomicAdd(&g_sum2, 0.0);
            double M = (double)N_CELLS * (double)H;
            double mean = S / M;
            double var = S2 / M - mean * mean;
            out[out_size - 1] = (float)var;
        }
    }
}

// ---------------- launcher ----------------
extern "C" void kernel_launch(void* const* d_in, const int* in_sizes, int n_in,
                              void* d_out, int out_size) {
    const float* x       = (const float*)d_in[0];
    const float* pump_W  = (const float*)d_in[1];
    const float* pump_b  = (const float*)d_in[2];
    const float* dec_W   = (const float*)d_in[3];
    const float* dec_b   = (const float*)d_in[4];
    const float* cs_re   = (const float*)d_in[5];
    const float* cs_im   = (const float*)d_in[6];
    const float* excited = (const float*)d_in[7];
    const float* phase_v = (const float*)d_in[8];
    const float* cav_re  = (const float*)d_in[9];
    const float* cav_im  = (const float*)d_in[10];
    const int*   nbr     = (const int*)d_in[11];
    float* out = (float*)d_out;

    k_rot<<<(N_CELLS * H / 4) / 256, 256>>>((const float4*)cs_re,
                                            (const float4*)cs_im,
                                            (const float4*)phase_v);
    k_pump<<<N_CELLS / 8, 256>>>(x, pump_W, pump_b, excited);
    k_couple<<<N_CELLS, 128>>>(nbr);
    k_emit<<<64, 128>>>();
    k_cav_update<<<1, 512>>>(cav_re, cav_im);
    k_decode<<<D, 128>>>(dec_W, dec_b, out);
    k_final<<<N_CELLS, 128>>>(out, out_size);
}

// round 10
// speedup vs baseline: 1.2299x; 1.0749x over previous
#include <cuda_runtime.h>
#include <cuda_fp16.h>
#include <math.h>
#include <stdint.h>

#define N_CELLS 16384
#define H 512
#define D 512
#define KNB 15

// ---------------- scratch ----------------
__device__ __align__(16) __half2 g_v  [N_CELLS * H];   // v = sqrt(|s|)*unit(s)
__device__ __align__(16) __half2 g_new[N_CELLS * H];
__device__ int    g_lasing[N_CELLS];
__device__ int    g_las_list[N_CELLS];
__device__ int    g_nlasing;
__device__ float  g_em_re[H];
__device__ float  g_em_im[H];
__device__ float  g_cavn_re[H];
__device__ float  g_cavn_im[H];
__device__ float  g_cav_phase[H];
__device__ double g_sum, g_sum2;
__device__ unsigned int g_done;

// ---------------- K1: pump -> lasing mask + compaction ----------------
__global__ void k_pump(const float* __restrict__ x,
                       const float* __restrict__ W,
                       const float* __restrict__ b,
                       const float* __restrict__ excited) {
    int warp = threadIdx.x >> 5;
    int lane = threadIdx.x & 31;
    int cell = blockIdx.x * 8 + warp;
    const float* w = W + (size_t)cell * D;
    float s = 0.f;
#pragma unroll
    for (int t = 0; t < D / 32; t++)
        s += x[lane + 32 * t] * w[lane + 32 * t];
#pragma unroll
    for (int o = 16; o; o >>= 1) s += __shfl_xor_sync(0xFFFFFFFFu, s, o);

    __shared__ int sflag[8];
    __shared__ int sbase;
    if (lane == 0) {
        float z = s + b[cell];
        float pump = 1.f / (1.f + expf(-z));
        float e = excited[cell] * 0.95f + pump * 0.05f;
        e = fminf(fmaxf(e, 0.f), 1.f);
        int las = (e > 0.5f) ? 1 : 0;
        g_lasing[cell] = las;
        sflag[warp] = las;
    }
    __syncthreads();
    if (threadIdx.x < 8) {
        unsigned m = __ballot_sync(0x000000FFu, sflag[threadIdx.x]);
        int total = __popc(m);
        if (threadIdx.x == 0 && total) sbase = atomicAdd(&g_nlasing, total);
        __syncwarp(0x000000FFu);
        if (sflag[threadIdx.x]) {
            int pos = sbase + __popc(m & ((1u << threadIdx.x) - 1u));
            g_las_list[pos] = blockIdx.x * 8 + threadIdx.x;
        }
    }
}

// ---------------- K2: rotate (Taylor) + scale to v = s/sqrt(|s|) ----------------
__global__ void k_rot(const float4* __restrict__ cr,
                      const float4* __restrict__ ci,
                      const float4* __restrict__ pv) {
    int i = blockIdx.x * blockDim.x + threadIdx.x;   // over N*H/4
    if (blockIdx.x == 0) {
        for (int j = threadIdx.x; j < H; j += blockDim.x) {
            g_em_re[j] = 0.f; g_em_im[j] = 0.f;
        }
        if (threadIdx.x == 0) {
            g_nlasing = 0; g_sum = 0.0; g_sum2 = 0.0; g_done = 0u;
        }
    }
    if (i >= (N_CELLS * H) / 4) return;
    float4 a4 = cr[i], b4 = ci[i], p4 = pv[i];
    float ax[4] = {a4.x, a4.y, a4.z, a4.w};
    float bx[4] = {b4.x, b4.y, b4.z, b4.w};
    float px[4] = {p4.x, p4.y, p4.z, p4.w};
    uint4 outp;
    unsigned int* op = (unsigned int*)&outp;
#pragma unroll
    for (int q = 0; q < 4; q++) {
        float ang = 0.1f * px[q];
        float a2 = ang * ang;
        float cs = 1.f - 0.5f * a2;
        float sn = ang * (1.f - a2 * (1.f / 6.f));
        float re = ax[q] * cs - bx[q] * sn;
        float im = ax[q] * sn + bx[q] * cs;
        float m2 = fmaxf(re * re + im * im, 1e-30f);
        float qm = rsqrtf(sqrtf(m2));               // |s|^(-1/2)
        __half2 h = __floats2half2_rn(re * qm, im * qm);
        op[q] = *(unsigned int*)&h;
    }
    *(uint4*)((unsigned int*)g_v + (size_t)i * 4) = outp;
}

// ---------------- K3: neighbor coupling (Gram-matrix, half2 SIMD) ----------
__global__ void __launch_bounds__(128) k_couple(const int* __restrict__ nbr) {
    int cell = blockIdx.x;
    int t = threadIdx.x;
    __shared__ int snb[16];
    if (t < KNB) snb[t] = nbr[cell * KNB + t];
    __syncthreads();

    int chbase = t * 4;
    const __half2 z2 = __floats2half2_rn(0.f, 0.f);
    __half2 sq0 = z2, sq1 = z2, sq2 = z2, sq3 = z2;
    __half2 xy01 = z2, xy23 = z2;

#pragma unroll 3
    for (int j = 0; j < KNB; j++) {
        const uint4 np = *(const uint4*)(g_v + (size_t)snb[j] * H + chbase);
        __half2 n0 = *(const __half2*)&np.x;
        __half2 n1 = *(const __half2*)&np.y;
        __half2 n2 = *(const __half2*)&np.z;
        __half2 n3 = *(const __half2*)&np.w;
        sq0 = __hfma2(n0, n0, sq0);
        sq1 = __hfma2(n1, n1, sq1);
        sq2 = __hfma2(n2, n2, sq2);
        sq3 = __hfma2(n3, n3, sq3);
        unsigned int p, q;
        p = __byte_perm(np.x, np.y, 0x5410);
        q = __byte_perm(np.x, np.y, 0x7632);
        xy01 = __hfma2(*(__half2*)&p, *(__half2*)&q, xy01);
        p = __byte_perm(np.z, np.w, 0x5410);
        q = __byte_perm(np.z, np.w, 0x7632);
        xy23 = __hfma2(*(__half2*)&p, *(__half2*)&q, xy23);
    }

    size_t base = (size_t)cell * H + chbase;
    uint4 vp = *(const uint4*)(g_v + base);
    float2 v[4];
    v[0] = __half22float2(*(const __half2*)&vp.x);
    v[1] = __half22float2(*(const __half2*)&vp.y);
    v[2] = __half22float2(*(const __half2*)&vp.z);
    v[3] = __half22float2(*(const __half2*)&vp.w);

    float2 sqf[4];
    sqf[0] = __half22float2(sq0); sqf[1] = __half22float2(sq1);
    sqf[2] = __half22float2(sq2); sqf[3] = __half22float2(sq3);
    float2 xya = __half22float2(xy01);
    float2 xyb = __half22float2(xy23);
    float sxy[4] = {xya.x, xya.y, xyb.x, xyb.y};

    const float CF = 0.3f * 0.1f / (float)KNB;  // 0.002
    uint4 outp;
    unsigned int* op = (unsigned int*)&outp;
#pragma unroll
    for (int qc = 0; qc < 4; qc++) {
        float vx = v[qc].x, vy = v[qc].y;
        float ir = vx * sqf[qc].x + vy * sxy[qc];
        float ii = vx * sxy[qc]   + vy * sqf[qc].y;
        float a2 = fmaxf(vx * vx + vy * vy, 1e-30f);
        float inv = rsqrtf(a2);
        float amp = a2 * inv;
        __half2 h = __floats2half2_rn(0.7f * amp * vx + CF * inv * ir,
                                      0.7f * amp * vy + CF * inv * ii);
        op[qc] = *(unsigned int*)&h;
    }
    *(uint4*)(g_new + base) = outp;
}

// ---------------- K4: emission over compacted list, 4-way MLP ----------------
__global__ void __launch_bounds__(128) k_emit() {
    int t = threadIdx.x;
    int nl = g_nlasing;
    float sr0 = 0, sr1 = 0, sr2 = 0, sr3 = 0, si0 = 0, si1 = 0, si2 = 0, si3 = 0;
    int any = 0;
    size_t toff = (size_t)t * 4;
    for (int i = blockIdx.x * 4; i < nl; i += gridDim.x * 4) {
        any = 1;
        int m = nl - i;   // >= 1
        // batch-load 4 independent rows (zero-fill beyond list end)
        uint4 p[4];
        int c0 = g_las_list[i];
        int c1 = (m > 1) ? g_las_list[i + 1] : -1;
        int c2 = (m > 2) ? g_las_list[i + 2] : -1;
        int c3 = (m > 3) ? g_las_list[i + 3] : -1;
        p[0] = *(const uint4*)(g_new + (size_t)c0 * H + toff);
        p[1] = (c1 >= 0) ? *(const uint4*)(g_new + (size_t)c1 * H + toff) : make_uint4(0,0,0,0);
        p[2] = (c2 >= 0) ? *(const uint4*)(g_new + (size_t)c2 * H + toff) : make_uint4(0,0,0,0);
        p[3] = (c3 >= 0) ? *(const uint4*)(g_new + (size_t)c3 * H + toff) : make_uint4(0,0,0,0);
#pragma unroll
        for (int u = 0; u < 4; u++) {
            float2 a = __half22float2(*(const __half2*)&p[u].x);
            float2 b = __half22float2(*(const __half2*)&p[u].y);
            float2 c = __half22float2(*(const __half2*)&p[u].z);
            float2 d = __half22float2(*(const __half2*)&p[u].w);
            sr0 += a.x; si0 += a.y;
            sr1 += b.x; si1 += b.y;
            sr2 += c.x; si2 += c.y;
            sr3 += d.x; si3 += d.y;
        }
    }
    if (any) {
        int h = t * 4;
        atomicAdd(&g_em_re[h + 0], sr0); atomicAdd(&g_em_re[h + 1], sr1);
        atomicAdd(&g_em_re[h + 2], sr2); atomicAdd(&g_em_re[h + 3], sr3);
        atomicAdd(&g_em_im[h + 0], si0); atomicAdd(&g_em_im[h + 1], si1);
        atomicAdd(&g_em_im[h + 2], si2); atomicAdd(&g_em_im[h + 3], si3);
    }
}

// ---------------- K5a: cavity update ----------------
__global__ void __launch_bounds__(512) k_cav_update(const float* __restrict__ cav_re,
                                                    const float* __restrict__ cav_im) {
    int t = threadIdx.x;
    int nl = g_nlasing;
    float inv = 1.f / fmaxf((float)nl, 1.f);
    float cr = cav_re[t], ci = cav_im[t];
    float nr = (nl > 0) ? 0.8f * cr + 0.2f * (g_em_re[t] * inv) : cr;
    float ni = (nl > 0) ? 0.8f * ci + 0.2f * (g_em_im[t] * inv) : ci;
    g_cavn_re[t] = nr;
    g_cavn_im[t] = ni;
    g_cav_phase[t] = atan2f(ci, cr);   // OLD cavity phase
}

// ---------------- K5b: decode GEMV ----------------
__global__ void __launch_bounds__(128) k_decode(const float* __restrict__ decW,
                                                const float* __restrict__ decb,
                                                float* __restrict__ out) {
    int d = blockIdx.x;
    int t = threadIdx.x;
    const float* w = decW + (size_t)d * (2 * H);
    float s = 0.f;
#pragma unroll
    for (int j = t; j < 2 * H; j += 128) {
        float v = (j < H) ? g_cavn_re[j] : g_cavn_im[j - H];
        s = fmaf(v, w[j], s);
    }
#pragma unroll
    for (int o = 16; o; o >>= 1) s += __shfl_xor_sync(0xFFFFFFFFu, s, o);
    __shared__ float red[4];
    if ((t & 31) == 0) red[t >> 5] = s;
    __syncthreads();
    if (t == 0) out[d] = red[0] + red[1] + red[2] + red[3] + decb[d];
}

// ---------------- K6: finalize + variance + fused tension ----------------
__global__ void __launch_bounds__(128) k_final(float* __restrict__ out, int out_size) {
    int cell = blockIdx.x;
    int t = threadIdx.x;
    int wid = t >> 5, lane = t & 31;
    __shared__ float wmax[4];
    __shared__ float ws[4], ws2[4];

    size_t base = (size_t)cell * H + (size_t)t * 4;
    uint4 p = *(const uint4*)(g_new + base);
    float2 c0 = __half22float2(*(const __half2*)&p.x);
    float2 c1 = __half22float2(*(const __half2*)&p.y);
    float2 c2 = __half22float2(*(const __half2*)&p.z);
    float2 c3 = __half22float2(*(const __half2*)&p.w);
    int las = g_lasing[cell];

    float amp[4];
    float re_[4] = {c0.x, c1.x, c2.x, c3.x};
    float im_[4] = {c0.y, c1.y, c2.y, c3.y};
    float mx = 0.f;
#pragma unroll
    for (int q = 0; q < 4; q++) {
        int h = t * 4 + q;
        float re = re_[q], im = im_[q];
        if (las) {
            float a = sqrtf(re * re + im * im);
            float ang = 0.3f * g_cav_phase[h] + 0.7f * atan2f(im, re);
            float sn, cs;
            __sincosf(ang, &sn, &cs);
            re = a * cs;
            im = a * sn;
        }
        re += 0.05f * g_cavn_re[h];
        im += 0.05f * g_cavn_im[h];
        amp[q] = sqrtf(re * re + im * im);
        mx = fmaxf(mx, amp[q]);
    }
#pragma unroll
    for (int o = 16; o; o >>= 1) mx = fmaxf(mx, __shfl_xor_sync(0xFFFFFFFFu, mx, o));
    if (lane == 0) wmax[wid] = mx;
    __syncthreads();
    float bmax = fmaxf(fmaxf(wmax[0], wmax[1]), fmaxf(wmax[2], wmax[3]));
    float inv = 1.f / (bmax + 1e-8f);

    float s = 0.f, s2 = 0.f;
#pragma unroll
    for (int q = 0; q < 4; q++) {
        float an = amp[q] * inv;
        s += an;
        s2 = fmaf(an, an, s2);
    }
#pragma unroll
    for (int o = 16; o; o >>= 1) {
        s  += __shfl_xor_sync(0xFFFFFFFFu, s, o);
        s2 += __shfl_xor_sync(0xFFFFFFFFu, s2, o);
    }
    if (lane == 0) { ws[wid] = s; ws2[wid] = s2; }
    __syncthreads();
    if (t == 0) {
        float bs  = ws[0] + ws[1] + ws[2] + ws[3];
        float bs2 = ws2[0] + ws2[1] + ws2[2] + ws2[3];
        atomicAdd(&g_sum,  (double)bs);
        atomicAdd(&g_sum2, (double)bs2);
        __threadfence();
        unsigned int done = atomicAdd(&g_done, 1u);
        if (done == gridDim.x - 1) {
            double S  = atomicAdd(&g_sum,  0.0);
            double S2 = atomicAdd(&g_sum2, 0.0);
            double M = (double)N_CELLS * (double)H;
            double mean = S / M;
            double var = S2 / M - mean * mean;
            out[out_size - 1] = (float)var;
        }
    }
}

// ---------------- launcher ----------------
extern "C" void kernel_launch(void* const* d_in, const int* in_sizes, int n_in,
                              void* d_out, int out_size) {
    const float* x       = (const float*)d_in[0];
    const float* pump_W  = (const float*)d_in[1];
    const float* pump_b  = (const float*)d_in[2];
    const float* dec_W   = (const float*)d_in[3];
    const float* dec_b   = (const float*)d_in[4];
    const float* cs_re   = (const float*)d_in[5];
    const float* cs_im   = (const float*)d_in[6];
    const float* excited = (const float*)d_in[7];
    const float* phase_v = (const float*)d_in[8];
    const float* cav_re  = (const float*)d_in[9];
    const float* cav_im  = (const float*)d_in[10];
    const int*   nbr     = (const int*)d_in[11];
    float* out = (float*)d_out;

    k_rot<<<(N_CELLS * H / 4) / 256, 256>>>((const float4*)cs_re,
                                            (const float4*)cs_im,
                                            (const float4*)phase_v);
    k_pump<<<N_CELLS / 8, 256>>>(x, pump_W, pump_b, excited);
    k_couple<<<N_CELLS, 128>>>(nbr);
    k_emit<<<64, 128>>>();
    k_cav_update<<<1, 512>>>(cav_re, cav_im);
    k_decode<<<D, 128>>>(dec_W, dec_b, out);
    k_final<<<N_CELLS, 128>>>(out, out_size);
}

// round 11
// speedup vs baseline: 1.2471x; 1.0139x over previous
#include <cuda_runtime.h>
#include <cuda_fp16.h>
#include <math.h>
#include <stdint.h>

#define N_CELLS 16384
#define H 512
#define D 512
#define KNB 15

// ---------------- scratch ----------------
__device__ __align__(16) __half2 g_v  [N_CELLS * H];   // v = sqrt(|s|)*unit(s)
__device__ __align__(16) __half2 g_new[N_CELLS * H];
__device__ int    g_lasing[N_CELLS];
__device__ int    g_las_list[N_CELLS];
__device__ int    g_nlasing;
__device__ float  g_em_re[H];
__device__ float  g_em_im[H];
__device__ float  g_cavn_re[H];
__device__ float  g_cavn_im[H];
__device__ float  g_cav_phase[H];
__device__ double g_sum, g_sum2;
__device__ unsigned int g_done;

// ---------------- K1: pump -> lasing mask + compaction ----------------
__global__ void k_pump(const float* __restrict__ x,
                       const float* __restrict__ W,
                       const float* __restrict__ b,
                       const float* __restrict__ excited) {
    int warp = threadIdx.x >> 5;
    int lane = threadIdx.x & 31;
    int cell = blockIdx.x * 8 + warp;
    const float* w = W + (size_t)cell * D;
    float s = 0.f;
#pragma unroll
    for (int t = 0; t < D / 32; t++)
        s += x[lane + 32 * t] * w[lane + 32 * t];
#pragma unroll
    for (int o = 16; o; o >>= 1) s += __shfl_xor_sync(0xFFFFFFFFu, s, o);

    __shared__ int sflag[8];
    __shared__ int sbase;
    if (lane == 0) {
        float z = s + b[cell];
        float pump = 1.f / (1.f + expf(-z));
        float e = excited[cell] * 0.95f + pump * 0.05f;
        e = fminf(fmaxf(e, 0.f), 1.f);
        int las = (e > 0.5f) ? 1 : 0;
        g_lasing[cell] = las;
        sflag[warp] = las;
    }
    __syncthreads();
    if (threadIdx.x < 8) {
        unsigned m = __ballot_sync(0x000000FFu, sflag[threadIdx.x]);
        int total = __popc(m);
        if (threadIdx.x == 0 && total) sbase = atomicAdd(&g_nlasing, total);
        __syncwarp(0x000000FFu);
        if (sflag[threadIdx.x]) {
            int pos = sbase + __popc(m & ((1u << threadIdx.x) - 1u));
            g_las_list[pos] = blockIdx.x * 8 + threadIdx.x;
        }
    }
}

// ---------------- K2: rotate (Taylor) + scale to v = s/sqrt(|s|) ----------------
__global__ void k_rot(const float4* __restrict__ cr,
                      const float4* __restrict__ ci,
                      const float4* __restrict__ pv) {
    int i = blockIdx.x * blockDim.x + threadIdx.x;   // over N*H/4
    if (blockIdx.x == 0) {
        for (int j = threadIdx.x; j < H; j += blockDim.x) {
            g_em_re[j] = 0.f; g_em_im[j] = 0.f;
        }
        if (threadIdx.x == 0) {
            g_nlasing = 0; g_sum = 0.0; g_sum2 = 0.0; g_done = 0u;
        }
    }
    if (i >= (N_CELLS * H) / 4) return;
    float4 a4 = cr[i], b4 = ci[i], p4 = pv[i];
    float ax[4] = {a4.x, a4.y, a4.z, a4.w};
    float bx[4] = {b4.x, b4.y, b4.z, b4.w};
    float px[4] = {p4.x, p4.y, p4.z, p4.w};
    uint4 outp;
    unsigned int* op = (unsigned int*)&outp;
#pragma unroll
    for (int q = 0; q < 4; q++) {
        float ang = 0.1f * px[q];
        float a2 = ang * ang;
        float cs = 1.f - 0.5f * a2;
        float sn = ang * (1.f - a2 * (1.f / 6.f));
        float re = ax[q] * cs - bx[q] * sn;
        float im = ax[q] * sn + bx[q] * cs;
        float m2 = fmaxf(re * re + im * im, 1e-30f);
        float qm = rsqrtf(sqrtf(m2));               // |s|^(-1/2)
        __half2 h = __floats2half2_rn(re * qm, im * qm);
        op[q] = *(unsigned int*)&h;
    }
    *(uint4*)((unsigned int*)g_v + (size_t)i * 4) = outp;
}

// ---------------- K3: neighbor coupling (Gram-matrix, half2 SIMD) ----------
__global__ void __launch_bounds__(128) k_couple(const int* __restrict__ nbr) {
    int cell = blockIdx.x;
    int t = threadIdx.x;
    __shared__ int snb[16];
    if (t < KNB) snb[t] = nbr[cell * KNB + t];
    __syncthreads();

    int chbase = t * 4;
    const __half2 z2 = __floats2half2_rn(0.f, 0.f);
    __half2 sq0 = z2, sq1 = z2, sq2 = z2, sq3 = z2;
    __half2 xy01 = z2, xy23 = z2;

#pragma unroll 3
    for (int j = 0; j < KNB; j++) {
        const uint4 np = *(const uint4*)(g_v + (size_t)snb[j] * H + chbase);
        __half2 n0 = *(const __half2*)&np.x;
        __half2 n1 = *(const __half2*)&np.y;
        __half2 n2 = *(const __half2*)&np.z;
        __half2 n3 = *(const __half2*)&np.w;
        sq0 = __hfma2(n0, n0, sq0);
        sq1 = __hfma2(n1, n1, sq1);
        sq2 = __hfma2(n2, n2, sq2);
        sq3 = __hfma2(n3, n3, sq3);
        unsigned int p, q;
        p = __byte_perm(np.x, np.y, 0x5410);
        q = __byte_perm(np.x, np.y, 0x7632);
        xy01 = __hfma2(*(__half2*)&p, *(__half2*)&q, xy01);
        p = __byte_perm(np.z, np.w, 0x5410);
        q = __byte_perm(np.z, np.w, 0x7632);
        xy23 = __hfma2(*(__half2*)&p, *(__half2*)&q, xy23);
    }

    size_t base = (size_t)cell * H + chbase;
    uint4 vp = *(const uint4*)(g_v + base);
    float2 v[4];
    v[0] = __half22float2(*(const __half2*)&vp.x);
    v[1] = __half22float2(*(const __half2*)&vp.y);
    v[2] = __half22float2(*(const __half2*)&vp.z);
    v[3] = __half22float2(*(const __half2*)&vp.w);

    float2 sqf[4];
    sqf[0] = __half22float2(sq0); sqf[1] = __half22float2(sq1);
    sqf[2] = __half22float2(sq2); sqf[3] = __half22float2(sq3);
    float2 xya = __half22float2(xy01);
    float2 xyb = __half22float2(xy23);
    float sxy[4] = {xya.x, xya.y, xyb.x, xyb.y};

    const float CF = 0.3f * 0.1f / (float)KNB;  // 0.002
    uint4 outp;
    unsigned int* op = (unsigned int*)&outp;
#pragma unroll
    for (int qc = 0; qc < 4; qc++) {
        float vx = v[qc].x, vy = v[qc].y;
        float ir = vx * sqf[qc].x + vy * sxy[qc];
        float ii = vx * sxy[qc]   + vy * sqf[qc].y;
        float a2 = fmaxf(vx * vx + vy * vy, 1e-30f);
        float inv = rsqrtf(a2);
        float amp = a2 * inv;
        __half2 h = __floats2half2_rn(0.7f * amp * vx + CF * inv * ir,
                                      0.7f * amp * vy + CF * inv * ii);
        op[qc] = *(unsigned int*)&h;
    }
    *(uint4*)(g_new + base) = outp;
}

// ---------------- K4: emission — contiguous chunk per block, batch-8 MLP ----
__global__ void __launch_bounds__(128) k_emit() {
    int t = threadIdx.x;
    int nl = g_nlasing;
    int chunk = (nl + gridDim.x - 1) / gridDim.x;
    int i0 = blockIdx.x * chunk;
    int i1 = min(i0 + chunk, nl);
    if (i0 >= i1) return;

    size_t toff = (size_t)t * 4;
    float sr0 = 0, sr1 = 0, sr2 = 0, sr3 = 0, si0 = 0, si1 = 0, si2 = 0, si3 = 0;

    for (int i = i0; i < i1; i += 8) {
        int m = i1 - i;
        int ids[8];
#pragma unroll
        for (int u = 0; u < 8; u++)
            ids[u] = (u < m) ? g_las_list[i + u] : -1;    // broadcast loads
        uint4 p[8];
#pragma unroll
        for (int u = 0; u < 8; u++)
            p[u] = (ids[u] >= 0) ? *(const uint4*)(g_new + (size_t)ids[u] * H + toff)
                                 : make_uint4(0, 0, 0, 0);
#pragma unroll
        for (int u = 0; u < 8; u++) {
            float2 a = __half22float2(*(const __half2*)&p[u].x);
            float2 b = __half22float2(*(const __half2*)&p[u].y);
            float2 c = __half22float2(*(const __half2*)&p[u].z);
            float2 d = __half22float2(*(const __half2*)&p[u].w);
            sr0 += a.x; si0 += a.y;
            sr1 += b.x; si1 += b.y;
            sr2 += c.x; si2 += c.y;
            sr3 += d.x; si3 += d.y;
        }
    }
    int h = t * 4;
    atomicAdd(&g_em_re[h + 0], sr0); atomicAdd(&g_em_re[h + 1], sr1);
    atomicAdd(&g_em_re[h + 2], sr2); atomicAdd(&g_em_re[h + 3], sr3);
    atomicAdd(&g_em_im[h + 0], si0); atomicAdd(&g_em_im[h + 1], si1);
    atomicAdd(&g_em_im[h + 2], si2); atomicAdd(&g_em_im[h + 3], si3);
}

// ---------------- K5a: cavity update ----------------
__global__ void __launch_bounds__(512) k_cav_update(const float* __restrict__ cav_re,
                                                    const float* __restrict__ cav_im) {
    int t = threadIdx.x;
    int nl = g_nlasing;
    float inv = 1.f / fmaxf((float)nl, 1.f);
    float cr = cav_re[t], ci = cav_im[t];
    float nr = (nl > 0) ? 0.8f * cr + 0.2f * (g_em_re[t] * inv) : cr;
    float ni = (nl > 0) ? 0.8f * ci + 0.2f * (g_em_im[t] * inv) : ci;
    g_cavn_re[t] = nr;
    g_cavn_im[t] = ni;
    g_cav_phase[t] = atan2f(ci, cr);   // OLD cavity phase
}

// ---------------- K5b: decode GEMV ----------------
__global__ void __launch_bounds__(128) k_decode(const float* __restrict__ decW,
                                                const float* __restrict__ decb,
                                                float* __restrict__ out) {
    int d = blockIdx.x;
    int t = threadIdx.x;
    const float* w = decW + (size_t)d * (2 * H);
    float s = 0.f;
#pragma unroll
    for (int j = t; j < 2 * H; j += 128) {
        float v = (j < H) ? g_cavn_re[j] : g_cavn_im[j - H];
        s = fmaf(v, w[j], s);
    }
#pragma unroll
    for (int o = 16; o; o >>= 1) s += __shfl_xor_sync(0xFFFFFFFFu, s, o);
    __shared__ float red[4];
    if ((t & 31) == 0) red[t >> 5] = s;
    __syncthreads();
    if (t == 0) out[d] = red[0] + red[1] + red[2] + red[3] + decb[d];
}

// ---------------- K6: finalize + variance + fused tension ----------------
__global__ void __launch_bounds__(128) k_final(float* __restrict__ out, int out_size) {
    int cell = blockIdx.x;
    int t = threadIdx.x;
    int wid = t >> 5, lane = t & 31;
    __shared__ float wmax[4];
    __shared__ float ws[4], ws2[4];

    size_t base = (size_t)cell * H + (size_t)t * 4;
    uint4 p = *(const uint4*)(g_new + base);
    float2 c0 = __half22float2(*(const __half2*)&p.x);
    float2 c1 = __half22float2(*(const __half2*)&p.y);
    float2 c2 = __half22float2(*(const __half2*)&p.z);
    float2 c3 = __half22float2(*(const __half2*)&p.w);
    int las = g_lasing[cell];

    float amp[4];
    float re_[4] = {c0.x, c1.x, c2.x, c3.x};
    float im_[4] = {c0.y, c1.y, c2.y, c3.y};
    float mx = 0.f;
#pragma unroll
    for (int q = 0; q < 4; q++) {
        int h = t * 4 + q;
        float re = re_[q], im = im_[q];
        if (las) {
            float a = sqrtf(re * re + im * im);
            float ang = 0.3f * g_cav_phase[h] + 0.7f * atan2f(im, re);
            float sn, cs;
            __sincosf(ang, &sn, &cs);
            re = a * cs;
            im = a * sn;
        }
        re += 0.05f * g_cavn_re[h];
        im += 0.05f * g_cavn_im[h];
        amp[q] = sqrtf(re * re + im * im);
        mx = fmaxf(mx, amp[q]);
    }
#pragma unroll
    for (int o = 16; o; o >>= 1) mx = fmaxf(mx, __shfl_xor_sync(0xFFFFFFFFu, mx, o));
    if (lane == 0) wmax[wid] = mx;
    __syncthreads();
    float bmax = fmaxf(fmaxf(wmax[0], wmax[1]), fmaxf(wmax[2], wmax[3]));
    float inv = 1.f / (bmax + 1e-8f);

    float s = 0.f, s2 = 0.f;
#pragma unroll
    for (int q = 0; q < 4; q++) {
        float an = amp[q] * inv;
        s += an;
        s2 = fmaf(an, an, s2);
    }
#pragma unroll
    for (int o = 16; o; o >>= 1) {
        s  += __shfl_xor_sync(0xFFFFFFFFu, s, o);
        s2 += __shfl_xor_sync(0xFFFFFFFFu, s2, o);
    }
    if (lane == 0) { ws[wid] = s; ws2[wid] = s2; }
    __syncthreads();
    if (t == 0) {
        float bs  = ws[0] + ws[1] + ws[2] + ws[3];
        float bs2 = ws2[0] + ws2[1] + ws2[2] + ws2[3];
        atomicAdd(&g_sum,  (double)bs);
        atomicAdd(&g_sum2, (double)bs2);
        __threadfence();
        unsigned int done = atomicAdd(&g_done, 1u);
        if (done == gridDim.x - 1) {
            double S  = atomicAdd(&g_sum,  0.0);
            double S2 = atomicAdd(&g_sum2, 0.0);
            double M = (double)N_CELLS * (double)H;
            double mean = S / M;
            double var = S2 / M - mean * mean;
            out[out_size - 1] = (float)var;
        }
    }
}

// ---------------- launcher ----------------
extern "C" void kernel_launch(void* const* d_in, const int* in_sizes, int n_in,
                              void* d_out, int out_size) {
    const float* x       = (const float*)d_in[0];
    const float* pump_W  = (const float*)d_in[1];
    const float* pump_b  = (const float*)d_in[2];
    const float* dec_W   = (const float*)d_in[3];
    const float* dec_b   = (const float*)d_in[4];
    const float* cs_re   = (const float*)d_in[5];
    const float* cs_im   = (const float*)d_in[6];
    const float* excited = (const float*)d_in[7];
    const float* phase_v = (const float*)d_in[8];
    const float* cav_re  = (const float*)d_in[9];
    const float* cav_im  = (const float*)d_in[10];
    const int*   nbr     = (const int*)d_in[11];
    float* out = (float*)d_out;

    k_rot<<<(N_CELLS * H / 4) / 256, 256>>>((const float4*)cs_re,
                                            (const float4*)cs_im,
                                            (const float4*)phase_v);
    k_pump<<<N_CELLS / 8, 256>>>(x, pump_W, pump_b, excited);
    k_couple<<<N_CELLS, 128>>>(nbr);
    k_emit<<<64, 128>>>();
    k_cav_update<<<1, 512>>>(cav_re, cav_im);
    k_decode<<<D, 128>>>(dec_W, dec_b, out);
    k_final<<<N_CELLS, 128>>>(out, out_size);
}